// round 2
// baseline (speedup 1.0000x reference)
#include <cuda_runtime.h>
#include <cuda_fp16.h>

// B=512, L=1000, H=128. 2-layer LSTM + linear head.
// Persistent: 128 CTAs x 512 threads, CTA owns batches 4c..4c+3 for all t.
// Thread g: matmul role = gate row g (j=g&127, type=g>>7) for 4 batches;
//           activation role = (batch=g>>7, hidden j=g&127), keeps c1,c2 in regs.
// fp16 weights: w_hh1 in smem, w_hh2 in registers, w_ih2 streamed from L2.
// Inner product: fma.rn.f32x2, lanes = even/odd-k partial sums.

typedef unsigned long long u64;

__device__ uint2 g_pw1[32 * 512];   // w_hh1 packed [m][g], 4 halves per uint2 (k=4m..4m+3)
__device__ uint2 g_pw2a[32 * 512];  // w_ih2 packed
__device__ uint2 g_pw2b[32 * 512];  // w_hh2 packed
__device__ float g_b1[512];         // b_ih1 + b_hh1
__device__ float g_b2[512];         // b_ih2 + b_hh2

__device__ __forceinline__ u64 pk(float lo, float hi) {
    u64 r; asm("mov.b64 %0,{%1,%2};" : "=l"(r) : "f"(lo), "f"(hi)); return r;
}
__device__ __forceinline__ void fma2(u64& d, u64 a, u64 b) {
    asm("fma.rn.f32x2 %0,%1,%2,%0;" : "+l"(d) : "l"(a), "l"(b));
}
__device__ __forceinline__ float f2sum(u64 a) {
    float lo, hi; asm("mov.b64 {%0,%1}, %2;" : "=f"(lo), "=f"(hi) : "l"(a)); return lo + hi;
}
__device__ __forceinline__ float sigf(float v) {
    return __fdividef(1.f, 1.f + __expf(-v));
}
__device__ __forceinline__ float tanh_f(float v) {
    return 2.f * __fdividef(1.f, 1.f + __expf(-2.f * v)) - 1.f;
}

// Accumulate k=4m..4m+3 of weight row (wv, 4 fp16) against h[b][k] for b=0..3.
__device__ __forceinline__ void acc4(uint2 wv, const float* __restrict__ h, int m,
                                     u64& a0, u64& a1, u64& a2, u64& a3) {
    __half2 wlo = *reinterpret_cast<__half2*>(&wv.x);
    __half2 whi = *reinterpret_cast<__half2*>(&wv.y);
    float2 f01 = __half22float2(wlo);
    float2 f23 = __half22float2(whi);
    u64 w01 = pk(f01.x, f01.y);
    u64 w23 = pk(f23.x, f23.y);
    const ulonglong2* hp = reinterpret_cast<const ulonglong2*>(h);  // 16B units
    ulonglong2 hv;
    hv = hp[m];      fma2(a0, w01, hv.x); fma2(a0, w23, hv.y);
    hv = hp[m + 32]; fma2(a1, w01, hv.x); fma2(a1, w23, hv.y);
    hv = hp[m + 64]; fma2(a2, w01, hv.x); fma2(a2, w23, hv.y);
    hv = hp[m + 96]; fma2(a3, w01, hv.x); fma2(a3, w23, hv.y);
}

__global__ void prep_kernel(const float* __restrict__ w_hh1,
                            const float* __restrict__ w_ih2,
                            const float* __restrict__ w_hh2,
                            const float* __restrict__ b_ih1,
                            const float* __restrict__ b_hh1,
                            const float* __restrict__ b_ih2,
                            const float* __restrict__ b_hh2) {
    int idx = blockIdx.x * blockDim.x + threadIdx.x;
    if (idx < 512) {
        g_b1[idx] = b_ih1[idx] + b_hh1[idx];
        g_b2[idx] = b_ih2[idx] + b_hh2[idx];
    }
    if (idx < 3 * 16384) {
        int mat = idx >> 14;
        int r = idx & 16383;
        int m = r >> 9, g = r & 511;
        const float* w = (mat == 0) ? w_hh1 : (mat == 1) ? w_ih2 : w_hh2;
        uint2* dst = (mat == 0) ? g_pw1 : (mat == 1) ? g_pw2a : g_pw2b;
        const float* src = w + g * 128 + 4 * m;
        __half2 h01 = __floats2half2_rn(src[0], src[1]);
        __half2 h23 = __floats2half2_rn(src[2], src[3]);
        uint2 v;
        v.x = *reinterpret_cast<unsigned*>(&h01);
        v.y = *reinterpret_cast<unsigned*>(&h23);
        dst[m * 512 + g] = v;
    }
}

#define SMEM_TOTAL 159424

__global__ void __launch_bounds__(512, 1)
lstm_main(const float* __restrict__ x, const float* __restrict__ w_ih1,
          const float* __restrict__ w_lin, const float* __restrict__ b_lin,
          float* __restrict__ out) {
    extern __shared__ char smch[];
    uint2* s_w1 = reinterpret_cast<uint2*>(smch);            // [32*512]  131072 B
    float* h1s = reinterpret_cast<float*>(smch + 131072);    // [4][128]    2048 B
    float* h2s = reinterpret_cast<float*>(smch + 133120);    // [4][128]    2048 B
    float* gb  = reinterpret_cast<float*>(smch + 135168);    // [4][128][4] 8192 B
    float* ps  = reinterpret_cast<float*>(smch + 143360);    // [16]          64 B
    float* xs  = reinterpret_cast<float*>(smch + 143424);    // [1000][4]  16000 B

    const int g = threadIdx.x;
    const int j = g & 127;
    const int ty = g >> 7;      // gate-type (matmul role) == batch (activation role)
    const int b0 = blockIdx.x * 4;

    // One-time loads: w_hh1 -> smem, x -> smem transposed [t][b]
    for (int i = g; i < 32 * 512; i += 512) s_w1[i] = g_pw1[i];
    for (int i = g; i < 4000; i += 512) xs[i] = x[(b0 + (i & 3)) * 1000 + (i >> 2)];
    h1s[g] = 0.f;
    h2s[g] = 0.f;

    float c1 = 0.f, c2 = 0.f;
    const float bias1 = g_b1[g];
    const float bias2 = g_b2[g];
    const float wi1 = w_ih1[g];
    const float wl = w_lin[j];
    const float bl = b_lin[0];

    uint2 rw[32];  // w_hh2 row g resident in registers
#pragma unroll
    for (int m = 0; m < 32; m++) rw[m] = g_pw2b[m * 512 + g];

    __syncthreads();

#pragma unroll 1
    for (int t = 0; t < 1000; t++) {
        float4 xv = *reinterpret_cast<const float4*>(xs + t * 4);

        // ---- layer 1 matmul: gates1[b][g] = b1 + wi1*x[b] + w_hh1[g,:].h1[b,:]
        u64 a0 = pk(fmaf(wi1, xv.x, bias1), 0.f);
        u64 a1 = pk(fmaf(wi1, xv.y, bias1), 0.f);
        u64 a2 = pk(fmaf(wi1, xv.z, bias1), 0.f);
        u64 a3 = pk(fmaf(wi1, xv.w, bias1), 0.f);
#pragma unroll
        for (int m = 0; m < 32; m++) acc4(s_w1[m * 512 + g], h1s, m, a0, a1, a2, a3);
        *reinterpret_cast<float4*>(gb + ty * 512 + j * 4) =
            make_float4(f2sum(a0), f2sum(a1), f2sum(a2), f2sum(a3));
        __syncthreads();

        // ---- layer 1 activation (thread = batch ty, hidden j)
        {
            float gi = gb[j * 4 + ty];
            float gf = gb[512 + j * 4 + ty];
            float gg = gb[1024 + j * 4 + ty];
            float go = gb[1536 + j * 4 + ty];
            float iv = sigf(gi), fv = sigf(gf), gv = tanh_f(gg), ov = sigf(go);
            c1 = fv * c1 + iv * gv;
            h1s[ty * 128 + j] = ov * tanh_f(c1);
        }
        __syncthreads();

        // ---- layer 2 matmul: gates2 = b2 + w_ih2.h1 + w_hh2.h2
        a0 = pk(bias2, 0.f); a1 = pk(bias2, 0.f); a2 = pk(bias2, 0.f); a3 = pk(bias2, 0.f);
        {
            uint2 wb[4];  // 4-deep L2 prefetch pipeline for streamed w_ih2
#pragma unroll
            for (int p = 0; p < 4; p++) wb[p] = g_pw2a[p * 512 + g];
#pragma unroll
            for (int m = 0; m < 32; m++) {
                uint2 wv = wb[m & 3];
                if (m < 28) wb[m & 3] = g_pw2a[(m + 4) * 512 + g];
                acc4(wv, h1s, m, a0, a1, a2, a3);
            }
        }
#pragma unroll
        for (int m = 0; m < 32; m++) acc4(rw[m], h2s, m, a0, a1, a2, a3);
        *reinterpret_cast<float4*>(gb + ty * 512 + j * 4) =
            make_float4(f2sum(a0), f2sum(a1), f2sum(a2), f2sum(a3));
        __syncthreads();

        // ---- layer 2 activation + output head
        float h2v;
        {
            float gi = gb[j * 4 + ty];
            float gf = gb[512 + j * 4 + ty];
            float gg = gb[1024 + j * 4 + ty];
            float go = gb[1536 + j * 4 + ty];
            float iv = sigf(gi), fv = sigf(gf), gv = tanh_f(gg), ov = sigf(go);
            c2 = fv * c2 + iv * gv;
            h2v = ov * tanh_f(c2);
            h2s[ty * 128 + j] = h2v;
        }
        float p = wl * h2v;  // partial of out[b=ty]
#pragma unroll
        for (int off = 16; off >= 1; off >>= 1) p += __shfl_xor_sync(0xffffffffu, p, off);
        if ((g & 31) == 0) ps[g >> 5] = p;   // warp w covers (b = w>>2, j-chunk = w&3)
        __syncthreads();
        if (g < 4)
            out[(b0 + g) * 1000 + t] = ps[g * 4] + ps[g * 4 + 1] + ps[g * 4 + 2] + ps[g * 4 + 3] + bl;
    }
}

extern "C" void kernel_launch(void* const* d_in, const int* in_sizes, int n_in,
                              void* d_out, int out_size) {
    const float* x     = (const float*)d_in[0];
    const float* w_ih1 = (const float*)d_in[1];
    const float* w_hh1 = (const float*)d_in[2];
    const float* b_ih1 = (const float*)d_in[3];
    const float* b_hh1 = (const float*)d_in[4];
    const float* w_ih2 = (const float*)d_in[5];
    const float* w_hh2 = (const float*)d_in[6];
    const float* b_ih2 = (const float*)d_in[7];
    const float* b_hh2 = (const float*)d_in[8];
    const float* w_lin = (const float*)d_in[9];
    const float* b_lin = (const float*)d_in[10];
    float* out = (float*)d_out;

    static bool attr_set = false;
    if (!attr_set) {
        cudaFuncSetAttribute(lstm_main, cudaFuncAttributeMaxDynamicSharedMemorySize, SMEM_TOTAL);
        attr_set = true;
    }

    prep_kernel<<<96, 512>>>(w_hh1, w_ih2, w_hh2, b_ih1, b_hh1, b_ih2, b_hh2);
    lstm_main<<<128, 512, SMEM_TOTAL>>>(x, w_ih1, w_lin, b_lin, out);
}